// round 15
// baseline (speedup 1.0000x reference)
#include <cuda_runtime.h>
#include <cuda_fp16.h>
#include <math.h>

#define B_  8
#define N_  1024
#define D_  1024
#define H_  16
#define HD_ 64
#define M_  (B_ * N_)
#define N3_ (3 * D_)

// ---------------- scratch ----------------------------------------------------
__device__ __half g_xh [(size_t)M_ * D_];
__device__ __half g_wqkvh[(size_t)D_ * N3_];
__device__ __half g_wouth[(size_t)D_ * D_];
__device__ __half g_qh [(size_t)B_ * H_ * N_ * HD_];
__device__ __half g_kh [(size_t)B_ * H_ * N_ * HD_];
__device__ __half g_vh [(size_t)B_ * H_ * N_ * HD_];
__device__ __half g_oh [(size_t)M_ * D_];
__device__ float  g_cos[N_ * 32];
__device__ float  g_sin[N_ * 32];

// ---------------- helpers -----------------------------------------------------
#define MMA_F16(d0,d1,d2,d3,a0,a1,a2,a3,b0,b1)                            \
    asm volatile(                                                          \
        "mma.sync.aligned.m16n8k16.row.col.f32.f16.f16.f32 "               \
        "{%0,%1,%2,%3},{%4,%5,%6,%7},{%8,%9},{%0,%1,%2,%3};\n"             \
        : "+f"(d0), "+f"(d1), "+f"(d2), "+f"(d3)                           \
        : "r"(a0), "r"(a1), "r"(a2), "r"(a3), "r"(b0), "r"(b1))

__device__ __forceinline__ void ldm_x4(unsigned& r0, unsigned& r1,
                                       unsigned& r2, unsigned& r3, unsigned a) {
    asm volatile("ldmatrix.sync.aligned.m8n8.x4.shared.b16 {%0,%1,%2,%3}, [%4];\n"
                 : "=r"(r0), "=r"(r1), "=r"(r2), "=r"(r3) : "r"(a));
}
__device__ __forceinline__ void ldm_x4_t(unsigned& r0, unsigned& r1,
                                         unsigned& r2, unsigned& r3, unsigned a) {
    asm volatile("ldmatrix.sync.aligned.m8n8.x4.trans.shared.b16 {%0,%1,%2,%3}, [%4];\n"
                 : "=r"(r0), "=r"(r1), "=r"(r2), "=r"(r3) : "r"(a));
}
__device__ __forceinline__ void cp16(unsigned smem_addr, const void* gptr) {
    asm volatile("cp.async.cg.shared.global [%0], [%1], 16;\n"
                 :: "r"(smem_addr), "l"(gptr));
}
#define CP_COMMIT() asm volatile("cp.async.commit_group;\n")
#define CP_WAIT(n)  asm volatile("cp.async.wait_group %0;\n" :: "n"(n))

__device__ __forceinline__ unsigned packh2(float a, float b) {
    __half2 h = __floats2half2_rn(a, b);
    return *(unsigned*)&h;
}

// -------- fused fp32 -> fp16 conversion + RoPE tables (one launch) -------------
#define X4_  (M_ * D_ / 4)
#define W14_ (D_ * N3_ / 4)
#define W24_ (D_ * D_ / 4)
#define CONV_N (X4_ + W14_ + W24_)
__global__ void f2h_all_kernel(const float* __restrict__ x,
                               const float* __restrict__ w1,
                               const float* __restrict__ w2) {
    int i = blockIdx.x * blockDim.x + threadIdx.x;
    if (i < CONV_N) {
        const float* src;
        __half* dst;
        int off;
        if (i < X4_) {
            src = x;  dst = g_xh;    off = i;
        } else if (i < X4_ + W14_) {
            src = w1; dst = g_wqkvh; off = i - X4_;
        } else {
            src = w2; dst = g_wouth; off = i - X4_ - W14_;
        }
        float4 v = ((const float4*)src)[off];
        ((__half2*)dst)[off * 2]     = __floats2half2_rn(v.x, v.y);
        ((__half2*)dst)[off * 2 + 1] = __floats2half2_rn(v.z, v.w);
    } else {
        int r = i - CONV_N;
        if (r >= N_ * 32) return;
        int n = r >> 5, j = r & 31;
        int pos = (j < 16) ? (n >> 5) : (n & 31);
        int jj  = (j < 16) ? j : (j - 16);
        float invf = exp2f(-(float)jj * (13.287712379549449f / 16.0f));
        float ang  = (float)pos * invf;
        g_cos[r] = cosf(ang);
        g_sin[r] = sinf(ang);
    }
}

// ====================== fp16 tensor-core GEMM + epilogues ======================
// Block 128x128, 8 warps = 4(M)x2(N), warp tile 32x64, occ 2.
// GBK=64 (16 k-tiles), 3-stage cp.async, refill hoisted to after barrier.
#define GBM 128
#define GBN 128
#define GBK 64
#define AST 72
#define BST 136
#define A_HALF (GBM * AST)     // 9216
#define B_HALF (GBK * BST)     // 8704
#define STG_HALF (A_HALF + B_HALF)
#define NSTAGE 3
#define GEMM_SMEM_BYTES (NSTAGE * STG_HALF * 2)   // 107520

template<int FUSED>
__global__ __launch_bounds__(256, 2)
void gemm_f16_core(const __half* __restrict__ A, const __half* __restrict__ Bm,
                   const float* __restrict__ bias, float* __restrict__ C,
                   const float* __restrict__ q_scale,
                   const float* __restrict__ k_scale,
                   int M, int N, int K)
{
    extern __shared__ __half sm[];
    const unsigned smem_base = (unsigned)__cvta_generic_to_shared(sm);

    const int tid  = threadIdx.x;
    const int warp = tid >> 5;
    const int lane = tid & 31;
    const int wm   = warp & 3;
    const int wn   = warp >> 2;
    const int g    = lane >> 2;
    const int t    = lane & 3;
    const int brow = blockIdx.y * GBM;
    const int bcol = blockIdx.x * GBN;

    float acc[2][8][4];
    #pragma unroll
    for (int i = 0; i < 2; i++)
        #pragma unroll
        for (int j = 0; j < 8; j++)
            #pragma unroll
            for (int c = 0; c < 4; c++) acc[i][j][c] = 0.f;

    const int T = K / GBK;

    auto issue = [&](int s, int k0) {
        unsigned abase = smem_base + (s * STG_HALF) * 2;
        unsigned bbase = abase + A_HALF * 2;
        #pragma unroll
        for (int it = 0; it < 4; it++) {
            int idx = tid + it * 256;
            int row = idx >> 3, cc = (idx & 7) * 8;
            cp16(abase + (row * AST + cc) * 2,
                 &A[(size_t)(brow + row) * K + k0 + cc]);
        }
        #pragma unroll
        for (int it = 0; it < 4; it++) {
            int idx = tid + it * 256;
            int row = idx >> 4, cc = (idx & 15) * 8;
            cp16(bbase + (row * BST + cc) * 2,
                 &Bm[(size_t)(k0 + row) * N + bcol + cc]);
        }
    };

    issue(0, 0);     CP_COMMIT();
    issue(1, GBK);   CP_COMMIT();

    const int a_r = (lane & 15);
    const int a_c = (lane >> 4) * 8;
    for (int ti = 0; ti < T; ti++) {
        CP_WAIT(1);
        __syncthreads();

        // refill freed stage immediately (barrier above guarantees all warps
        // finished computing it in iteration ti-1)
        if (ti + 2 < T) { issue((ti + 2) % 3, (ti + 2) * GBK); }
        CP_COMMIT();

        int cs = ti % 3;
        unsigned abase = smem_base + (cs * STG_HALF) * 2;
        unsigned bbase = abase + A_HALF * 2;

        #pragma unroll
        for (int ks = 0; ks < 4; ks++) {
            const int kb = ks * 16;
            unsigned af[2][4], bf[8][2];
            #pragma unroll
            for (int i = 0; i < 2; i++) {
                int m0 = wm * 32 + i * 16;
                ldm_x4(af[i][0], af[i][1], af[i][2], af[i][3],
                       abase + ((m0 + a_r) * AST + kb + a_c) * 2);
            }
            #pragma unroll
            for (int jp = 0; jp < 4; jp++) {
                int n0 = wn * 64 + jp * 16;
                unsigned r0, r1, r2, r3;
                ldm_x4_t(r0, r1, r2, r3,
                         bbase + ((kb + a_r) * BST + n0 + a_c) * 2);
                bf[jp * 2][0]     = r0; bf[jp * 2][1]     = r1;
                bf[jp * 2 + 1][0] = r2; bf[jp * 2 + 1][1] = r3;
            }
            #pragma unroll
            for (int i = 0; i < 2; i++)
                #pragma unroll
                for (int j = 0; j < 8; j++)
                    MMA_F16(acc[i][j][0], acc[i][j][1], acc[i][j][2], acc[i][j][3],
                            af[i][0], af[i][1], af[i][2], af[i][3],
                            bf[j][0], bf[j][1]);
        }
    }

    float bb[16];
    #pragma unroll
    for (int j = 0; j < 8; j++) {
        bb[j * 2]     = bias[bcol + wn * 64 + j * 8 + t * 2];
        bb[j * 2 + 1] = bias[bcol + wn * 64 + j * 8 + t * 2 + 1];
    }
    #pragma unroll
    for (int i = 0; i < 2; i++)
        #pragma unroll
        for (int j = 0; j < 8; j++) {
            acc[i][j][0] += bb[j * 2]; acc[i][j][1] += bb[j * 2 + 1];
            acc[i][j][2] += bb[j * 2]; acc[i][j][3] += bb[j * 2 + 1];
        }

    if (FUSED == 0) {
        #pragma unroll
        for (int i = 0; i < 2; i++) {
            int row = brow + wm * 32 + i * 16 + g;
            #pragma unroll
            for (int j = 0; j < 8; j++) {
                int col = bcol + wn * 64 + j * 8 + t * 2;
                float2 v0 = { acc[i][j][0], acc[i][j][1] };
                float2 v1 = { acc[i][j][2], acc[i][j][3] };
                *(float2*)&C[(size_t)row * N + col]       = v0;
                *(float2*)&C[(size_t)(row + 8) * N + col] = v1;
            }
        }
        return;
    }

    const int region = blockIdx.x >> 3;
    const int h      = ((blockIdx.x & 7) << 1) | wn;

    if (region == 2) {
        #pragma unroll
        for (int i = 0; i < 2; i++) {
            int grow = brow + wm * 32 + i * 16 + g;
            int nn = grow & (N_ - 1), bb_ = grow >> 10;
            size_t dst0 = ((size_t)(bb_ * H_ + h) * N_ + nn) * HD_;
            size_t dst1 = dst0 + 8 * HD_;
            #pragma unroll
            for (int j = 0; j < 8; j++) {
                int d = j * 8 + t * 2;
                *(__half2*)&g_vh[dst0 + d] = __floats2half2_rn(acc[i][j][0], acc[i][j][1]);
                *(__half2*)&g_vh[dst1 + d] = __floats2half2_rn(acc[i][j][2], acc[i][j][3]);
            }
        }
    } else {
        const float* scv = (region == 0) ? q_scale : k_scale;
        __half* outp     = (region == 0) ? g_qh : g_kh;
        const float rsmul = (region == 0) ? 0.125f : 1.0f;
        float scr[16];
        #pragma unroll
        for (int j = 0; j < 8; j++) {
            scr[j * 2]     = scv[j * 8 + t * 2];
            scr[j * 2 + 1] = scv[j * 8 + t * 2 + 1];
        }
        #pragma unroll
        for (int i = 0; i < 2; i++) {
            float ss0 = 0.f, ss1 = 0.f;
            #pragma unroll
            for (int j = 0; j < 8; j++) {
                ss0 += acc[i][j][0] * acc[i][j][0] + acc[i][j][1] * acc[i][j][1];
                ss1 += acc[i][j][2] * acc[i][j][2] + acc[i][j][3] * acc[i][j][3];
            }
            ss0 += __shfl_xor_sync(0xffffffffu, ss0, 1);
            ss0 += __shfl_xor_sync(0xffffffffu, ss0, 2);
            ss1 += __shfl_xor_sync(0xffffffffu, ss1, 1);
            ss1 += __shfl_xor_sync(0xffffffffu, ss1, 2);
            float rs0 = rsqrtf(ss0 * (1.0f / HD_) + 1e-6f) * rsmul;
            float rs1 = rsqrtf(ss1 * (1.0f / HD_) + 1e-6f) * rsmul;

            int grow = brow + wm * 32 + i * 16 + g;
            int nn = grow & (N_ - 1), bb_ = grow >> 10;
            size_t dst0 = ((size_t)(bb_ * H_ + h) * N_ + nn) * HD_;
            size_t dst1 = dst0 + 8 * HD_;
            #pragma unroll
            for (int j = 0; j < 4; j++) {
                int d = j * 8 + t * 2;
                float c00 = g_cos[nn * 32 + d],           s00 = g_sin[nn * 32 + d];
                float c01 = g_cos[nn * 32 + d + 1],       s01 = g_sin[nn * 32 + d + 1];
                float c10 = g_cos[(nn + 8) * 32 + d],     s10 = g_sin[(nn + 8) * 32 + d];
                float c11 = g_cos[(nn + 8) * 32 + d + 1], s11 = g_sin[(nn + 8) * 32 + d + 1];
                float a0 = acc[i][j][0] * rs0 * scr[j * 2];
                float a1 = acc[i][j][1] * rs0 * scr[j * 2 + 1];
                float p0 = acc[i][j + 4][0] * rs0 * scr[(j + 4) * 2];
                float p1 = acc[i][j + 4][1] * rs0 * scr[(j + 4) * 2 + 1];
                *(__half2*)&outp[dst0 + d]      = __floats2half2_rn(a0 * c00 - p0 * s00, a1 * c01 - p1 * s01);
                *(__half2*)&outp[dst0 + d + 32] = __floats2half2_rn(a0 * s00 + p0 * c00, a1 * s01 + p1 * c01);
                float e0 = acc[i][j][2] * rs1 * scr[j * 2];
                float e1 = acc[i][j][3] * rs1 * scr[j * 2 + 1];
                float q0 = acc[i][j + 4][2] * rs1 * scr[(j + 4) * 2];
                float q1 = acc[i][j + 4][3] * rs1 * scr[(j + 4) * 2 + 1];
                *(__half2*)&outp[dst1 + d]      = __floats2half2_rn(e0 * c10 - q0 * s10, e1 * c11 - q1 * s11);
                *(__half2*)&outp[dst1 + d + 32] = __floats2half2_rn(e0 * s10 + q0 * c10, e1 * s11 + q1 * c11);
            }
        }
    }
}

// ====== fp16 flash attention: 4 warps x 32 rows, ones-column, occ 3 ===========
#define KVST 88
#define KV_TILE_HALF (64 * KVST)
#define ATTN_SMEM_BYTES (6 * KV_TILE_HALF * 2)   // 67584

__global__ __launch_bounds__(128, 3)
void attn_f16_kernel()
{
    extern __shared__ __half asm_[];
    const unsigned smem_base = (unsigned)__cvta_generic_to_shared(asm_);

    const int tid  = threadIdx.x;
    const int warp = tid >> 5;
    const int lane = tid & 31;
    const int g    = lane >> 2;
    const int t    = lane & 3;
    const int bh   = blockIdx.y;
    const int qbase = blockIdx.x * 128 + warp * 32;
    const size_t base = (size_t)bh * N_ * HD_;
    const float LOG2E = 1.44269504f;

    for (int i = tid; i < 3 * 64; i += 128) {
        int buf = i >> 6, row = i & 63;
        __half* p = asm_ + (size_t)(3 + buf) * KV_TILE_HALF + row * KVST + 64;
        p[0] = __float2half(1.0f);
        #pragma unroll
        for (int j = 1; j < 8; j++) p[j] = __float2half(0.0f);
    }

    unsigned qf[2][4][4];
    #pragma unroll
    for (int mt = 0; mt < 2; mt++) {
        const __half* Q0 = g_qh + base + (size_t)(qbase + mt * 16 + g) * HD_;
        const __half* Q1 = Q0 + 8 * HD_;
        #pragma unroll
        for (int kk = 0; kk < 4; kk++) {
            qf[mt][kk][0] = *(const unsigned*)&Q0[kk * 16 + 2 * t];
            qf[mt][kk][1] = *(const unsigned*)&Q1[kk * 16 + 2 * t];
            qf[mt][kk][2] = *(const unsigned*)&Q0[kk * 16 + 8 + 2 * t];
            qf[mt][kk][3] = *(const unsigned*)&Q1[kk * 16 + 8 + 2 * t];
        }
    }

    float of[2][8][4];
    float ofl[2][4];
    #pragma unroll
    for (int mt = 0; mt < 2; mt++) {
        #pragma unroll
        for (int j = 0; j < 8; j++)
            #pragma unroll
            for (int c = 0; c < 4; c++) of[mt][j][c] = 0.f;
        #pragma unroll
        for (int c = 0; c < 4; c++) ofl[mt][c] = 0.f;
    }
    float mrow[2][2] = {{-1e30f, -1e30f}, {-1e30f, -1e30f}};

    auto issue_tile = [&](int buf, int tile) {
        unsigned kb = smem_base + buf * KV_TILE_HALF * 2;
        unsigned vb = smem_base + (3 + buf) * KV_TILE_HALF * 2;
        const __half* kg = g_kh + base + (size_t)tile * 64 * HD_;
        const __half* vg = g_vh + base + (size_t)tile * 64 * HD_;
        #pragma unroll
        for (int it = 0; it < 4; it++) {
            int idx = tid + it * 128;
            int row = idx >> 3, cc = (idx & 7) * 8;
            cp16(kb + (row * KVST + cc) * 2, kg + row * HD_ + cc);
            cp16(vb + (row * KVST + cc) * 2, vg + row * HD_ + cc);
        }
    };

    issue_tile(0, 0); CP_COMMIT();
    issue_tile(1, 1); CP_COMMIT();

    const int lr = lane & 15;
    const int lc = (lane >> 4) * 8;

    for (int tile = 0; tile < N_ / 64; tile++) {
        CP_WAIT(1);
        __syncthreads();

        int bufi = tile % 3;
        unsigned kbuf = smem_base + bufi * KV_TILE_HALF * 2;
        unsigned vbuf = smem_base + (3 + bufi) * KV_TILE_HALF * 2;

        float sacc[2][8][4];
        #pragma unroll
        for (int mt = 0; mt < 2; mt++)
            #pragma unroll
            for (int j = 0; j < 8; j++)
                #pragma unroll
                for (int c = 0; c < 4; c++) sacc[mt][j][c] = 0.f;

        #pragma unroll
        for (int kk = 0; kk < 4; kk++) {
            #pragma unroll
            for (int jp = 0; jp < 4; jp++) {
                unsigned r0, r1, r2, r3;
                int krow = jp * 16 + ((lane >> 3) & 1) * 8 + (lane & 7);
                ldm_x4(r0, r1, r2, r3,
                       kbuf + (krow * KVST + kk * 16 + lc) * 2);
                MMA_F16(sacc[0][jp*2][0], sacc[0][jp*2][1], sacc[0][jp*2][2], sacc[0][jp*2][3],
                        qf[0][kk][0], qf[0][kk][1], qf[0][kk][2], qf[0][kk][3], r0, r2);
                MMA_F16(sacc[0][jp*2+1][0], sacc[0][jp*2+1][1], sacc[0][jp*2+1][2], sacc[0][jp*2+1][3],
                        qf[0][kk][0], qf[0][kk][1], qf[0][kk][2], qf[0][kk][3], r1, r3);
                MMA_F16(sacc[1][jp*2][0], sacc[1][jp*2][1], sacc[1][jp*2][2], sacc[1][jp*2][3],
                        qf[1][kk][0], qf[1][kk][1], qf[1][kk][2], qf[1][kk][3], r0, r2);
                MMA_F16(sacc[1][jp*2+1][0], sacc[1][jp*2+1][1], sacc[1][jp*2+1][2], sacc[1][jp*2+1][3],
                        qf[1][kk][0], qf[1][kk][1], qf[1][kk][2], qf[1][kk][3], r1, r3);
            }
        }

        unsigned ph2[2][8][2];
        #pragma unroll
        for (int mt = 0; mt < 2; mt++) {
            float mx0 = -1e30f, mx1 = -1e30f;
            #pragma unroll
            for (int j = 0; j < 8; j++) {
                mx0 = fmaxf(mx0, fmaxf(sacc[mt][j][0], sacc[mt][j][1]));
                mx1 = fmaxf(mx1, fmaxf(sacc[mt][j][2], sacc[mt][j][3]));
            }
            mx0 = fmaxf(mx0, __shfl_xor_sync(0xffffffffu, mx0, 1));
            mx0 = fmaxf(mx0, __shfl_xor_sync(0xffffffffu, mx0, 2));
            mx1 = fmaxf(mx1, __shfl_xor_sync(0xffffffffu, mx1, 1));
            mx1 = fmaxf(mx1, __shfl_xor_sync(0xffffffffu, mx1, 2));

            float mn0 = fmaxf(mrow[mt][0], mx0);
            float mn1 = fmaxf(mrow[mt][1], mx1);
            float corr0 = __expf(mrow[mt][0] - mn0);
            float corr1 = __expf(mrow[mt][1] - mn1);
            mrow[mt][0] = mn0; mrow[mt][1] = mn1;

            float me0 = mn0 * LOG2E, me1 = mn1 * LOG2E;
            #pragma unroll
            for (int j = 0; j < 8; j++) {
                float d0 = fmaf(sacc[mt][j][0], LOG2E, -me0);
                float d1 = fmaf(sacc[mt][j][1], LOG2E, -me0);
                float d2 = fmaf(sacc[mt][j][2], LOG2E, -me1);
                float d3 = fmaf(sacc[mt][j][3], LOG2E, -me1);
                unsigned u0 = packh2(d0, d1);
                unsigned u1 = packh2(d2, d3);
                asm("ex2.approx.f16x2 %0, %0;" : "+r"(u0));
                asm("ex2.approx.f16x2 %0, %0;" : "+r"(u1));
                ph2[mt][j][0] = u0;
                ph2[mt][j][1] = u1;
            }

            #pragma unroll
            for (int j = 0; j < 8; j++) {
                of[mt][j][0] *= corr0; of[mt][j][1] *= corr0;
                of[mt][j][2] *= corr1; of[mt][j][3] *= corr1;
            }
            ofl[mt][0] *= corr0; ofl[mt][1] *= corr0;
            ofl[mt][2] *= corr1; ofl[mt][3] *= corr1;
        }

        #pragma unroll
        for (int kk = 0; kk < 4; kk++) {
            #pragma unroll
            for (int jp = 0; jp < 4; jp++) {
                unsigned r0, r1, r2, r3;
                ldm_x4_t(r0, r1, r2, r3,
                         vbuf + ((kk * 16 + lr) * KVST + jp * 16 + lc) * 2);
                #pragma unroll
                for (int mt = 0; mt < 2; mt++) {
                    MMA_F16(of[mt][jp*2][0], of[mt][jp*2][1], of[mt][jp*2][2], of[mt][jp*2][3],
                            ph2[mt][kk*2][0], ph2[mt][kk*2][1],
                            ph2[mt][kk*2+1][0], ph2[mt][kk*2+1][1], r0, r1);
                    MMA_F16(of[mt][jp*2+1][0], of[mt][jp*2+1][1], of[mt][jp*2+1][2], of[mt][jp*2+1][3],
                            ph2[mt][kk*2][0], ph2[mt][kk*2][1],
                            ph2[mt][kk*2+1][0], ph2[mt][kk*2+1][1], r2, r3);
                }
            }
            {
                unsigned r0, r1, r2, r3;
                ldm_x4_t(r0, r1, r2, r3,
                         vbuf + ((kk * 16 + lr) * KVST + 64 + lc) * 2);
                #pragma unroll
                for (int mt = 0; mt < 2; mt++)
                    MMA_F16(ofl[mt][0], ofl[mt][1], ofl[mt][2], ofl[mt][3],
                            ph2[mt][kk*2][0], ph2[mt][kk*2][1],
                            ph2[mt][kk*2+1][0], ph2[mt][kk*2+1][1], r0, r1);
            }
        }

        if (tile + 2 < N_ / 64) issue_tile((tile + 2) % 3, tile + 2);
        CP_COMMIT();
    }

    const int b = bh >> 4, h = bh & 15;
    const int srcl = lane & 28;
    #pragma unroll
    for (int mt = 0; mt < 2; mt++) {
        float l0 = __shfl_sync(0xffffffffu, ofl[mt][0], srcl);
        float l1 = __shfl_sync(0xffffffffu, ofl[mt][2], srcl);
        float inv0 = 1.0f / l0;
        float inv1 = 1.0f / l1;
        size_t row0 = ((size_t)b * N_ + qbase + mt * 16 + g) * D_ + h * HD_;
        size_t row1 = row0 + (size_t)8 * D_;
        #pragma unroll
        for (int j = 0; j < 8; j++) {
            int d = j * 8 + t * 2;
            *(__half2*)&g_oh[row0 + d] = __floats2half2_rn(of[mt][j][0] * inv0, of[mt][j][1] * inv0);
            *(__half2*)&g_oh[row1 + d] = __floats2half2_rn(of[mt][j][2] * inv1, of[mt][j][3] * inv1);
        }
    }
}

// ---------------- launch ---------------------------------------------------------
extern "C" void kernel_launch(void* const* d_in, const int* in_sizes, int n_in,
                              void* d_out, int out_size)
{
    const float* x       = (const float*)d_in[0];
    const float* Wqkv    = (const float*)d_in[1];
    const float* bqkv    = (const float*)d_in[2];
    const float* Wout    = (const float*)d_in[3];
    const float* bout    = (const float*)d_in[4];
    const float* q_scale = (const float*)d_in[5];
    const float* k_scale = (const float*)d_in[6];
    float* out = (float*)d_out;

    __half *xh_p, *wqkvh_p, *wouth_p, *oh_p;
    cudaGetSymbolAddress((void**)&xh_p,    g_xh);
    cudaGetSymbolAddress((void**)&wqkvh_p, g_wqkvh);
    cudaGetSymbolAddress((void**)&wouth_p, g_wouth);
    cudaGetSymbolAddress((void**)&oh_p,    g_oh);

    cudaFuncSetAttribute(gemm_f16_core<0>,
                         cudaFuncAttributeMaxDynamicSharedMemorySize, GEMM_SMEM_BYTES);
    cudaFuncSetAttribute(gemm_f16_core<1>,
                         cudaFuncAttributeMaxDynamicSharedMemorySize, GEMM_SMEM_BYTES);
    cudaFuncSetAttribute(attn_f16_kernel,
                         cudaFuncAttributeMaxDynamicSharedMemorySize, ATTN_SMEM_BYTES);

    int total_n = CONV_N + N_ * 32;
    f2h_all_kernel<<<(total_n + 255) / 256, 256>>>(x, Wqkv, Wout);

    dim3 g1(N3_ / GBN, M_ / GBM);
    gemm_f16_core<1><<<g1, 256, GEMM_SMEM_BYTES>>>(
        xh_p, wqkvh_p, bqkv, nullptr, q_scale, k_scale, M_, N3_, D_);

    attn_f16_kernel<<<dim3(N_ / 128, B_ * H_), 128, ATTN_SMEM_BYTES>>>();

    dim3 g2(D_ / GBN, M_ / GBM);
    gemm_f16_core<0><<<g2, 256, GEMM_SMEM_BYTES>>>(
        oh_p, wouth_p, bout, out, nullptr, nullptr, M_, D_, D_);
}

// round 16
// speedup vs baseline: 1.7264x; 1.7264x over previous
#include <cuda_runtime.h>
#include <cuda_fp16.h>
#include <math.h>

#define B_  8
#define N_  1024
#define D_  1024
#define H_  16
#define HD_ 64
#define M_  (B_ * N_)
#define N3_ (3 * D_)

// ---------------- scratch ----------------------------------------------------
__device__ __half g_xh [(size_t)M_ * D_];
__device__ __half g_wqkvh[(size_t)D_ * N3_];
__device__ __half g_wouth[(size_t)D_ * D_];
__device__ __half g_qh [(size_t)B_ * H_ * N_ * HD_];
__device__ __half g_kh [(size_t)B_ * H_ * N_ * HD_];
__device__ __half g_vh [(size_t)B_ * H_ * N_ * HD_];
__device__ __half g_oh [(size_t)M_ * D_];
__device__ float  g_cos[N_ * 32];
__device__ float  g_sin[N_ * 32];

// ---------------- helpers -----------------------------------------------------
#define MMA_F16(d0,d1,d2,d3,a0,a1,a2,a3,b0,b1)                            \
    asm volatile(                                                          \
        "mma.sync.aligned.m16n8k16.row.col.f32.f16.f16.f32 "               \
        "{%0,%1,%2,%3},{%4,%5,%6,%7},{%8,%9},{%0,%1,%2,%3};\n"             \
        : "+f"(d0), "+f"(d1), "+f"(d2), "+f"(d3)                           \
        : "r"(a0), "r"(a1), "r"(a2), "r"(a3), "r"(b0), "r"(b1))

__device__ __forceinline__ void ldm_x4(unsigned& r0, unsigned& r1,
                                       unsigned& r2, unsigned& r3, unsigned a) {
    asm volatile("ldmatrix.sync.aligned.m8n8.x4.shared.b16 {%0,%1,%2,%3}, [%4];\n"
                 : "=r"(r0), "=r"(r1), "=r"(r2), "=r"(r3) : "r"(a));
}
__device__ __forceinline__ void ldm_x4_t(unsigned& r0, unsigned& r1,
                                         unsigned& r2, unsigned& r3, unsigned a) {
    asm volatile("ldmatrix.sync.aligned.m8n8.x4.trans.shared.b16 {%0,%1,%2,%3}, [%4];\n"
                 : "=r"(r0), "=r"(r1), "=r"(r2), "=r"(r3) : "r"(a));
}
__device__ __forceinline__ void cp16(unsigned smem_addr, const void* gptr) {
    asm volatile("cp.async.cg.shared.global [%0], [%1], 16;\n"
                 :: "r"(smem_addr), "l"(gptr));
}
#define CP_COMMIT() asm volatile("cp.async.commit_group;\n")
#define CP_WAIT(n)  asm volatile("cp.async.wait_group %0;\n" :: "n"(n))

__device__ __forceinline__ unsigned packh2(float a, float b) {
    __half2 h = __floats2half2_rn(a, b);
    return *(unsigned*)&h;
}

// -------- fused fp32 -> fp16 conversion + RoPE tables (one launch) -------------
#define X4_  (M_ * D_ / 4)
#define W14_ (D_ * N3_ / 4)
#define W24_ (D_ * D_ / 4)
#define CONV_N (X4_ + W14_ + W24_)
__global__ void f2h_all_kernel(const float* __restrict__ x,
                               const float* __restrict__ w1,
                               const float* __restrict__ w2) {
    int i = blockIdx.x * blockDim.x + threadIdx.x;
    if (i < CONV_N) {
        const float* src;
        __half* dst;
        int off;
        if (i < X4_) {
            src = x;  dst = g_xh;    off = i;
        } else if (i < X4_ + W14_) {
            src = w1; dst = g_wqkvh; off = i - X4_;
        } else {
            src = w2; dst = g_wouth; off = i - X4_ - W14_;
        }
        float4 v = ((const float4*)src)[off];
        ((__half2*)dst)[off * 2]     = __floats2half2_rn(v.x, v.y);
        ((__half2*)dst)[off * 2 + 1] = __floats2half2_rn(v.z, v.w);
    } else {
        int r = i - CONV_N;
        if (r >= N_ * 32) return;
        int n = r >> 5, j = r & 31;
        int pos = (j < 16) ? (n >> 5) : (n & 31);
        int jj  = (j < 16) ? j : (j - 16);
        float invf = exp2f(-(float)jj * (13.287712379549449f / 16.0f));
        float ang  = (float)pos * invf;
        g_cos[r] = cosf(ang);
        g_sin[r] = sinf(ang);
    }
}

// ====================== fp16 tensor-core GEMM + epilogues ======================
// Block 128x128, 8 warps = 4(M)x2(N), warp tile 32x64, occ 2.
// GBK=64 (16 k-tiles), 3-stage cp.async, refill interleaved after first ks chunk.
#define GBM 128
#define GBN 128
#define GBK 64
#define AST 72
#define BST 136
#define A_HALF (GBM * AST)     // 9216
#define B_HALF (GBK * BST)     // 8704
#define STG_HALF (A_HALF + B_HALF)
#define NSTAGE 3
#define GEMM_SMEM_BYTES (NSTAGE * STG_HALF * 2)   // 107520

template<int FUSED>
__global__ __launch_bounds__(256, 2)
void gemm_f16_core(const __half* __restrict__ A, const __half* __restrict__ Bm,
                   const float* __restrict__ bias, float* __restrict__ C,
                   const float* __restrict__ q_scale,
                   const float* __restrict__ k_scale,
                   int M, int N, int K)
{
    extern __shared__ __half sm[];
    const unsigned smem_base = (unsigned)__cvta_generic_to_shared(sm);

    const int tid  = threadIdx.x;
    const int warp = tid >> 5;
    const int lane = tid & 31;
    const int wm   = warp & 3;
    const int wn   = warp >> 2;
    const int g    = lane >> 2;
    const int t    = lane & 3;
    const int brow = blockIdx.y * GBM;
    const int bcol = blockIdx.x * GBN;

    float acc[2][8][4];
    #pragma unroll
    for (int i = 0; i < 2; i++)
        #pragma unroll
        for (int j = 0; j < 8; j++)
            #pragma unroll
            for (int c = 0; c < 4; c++) acc[i][j][c] = 0.f;

    const int T = K / GBK;

    auto issue = [&](int s, int k0) {
        unsigned abase = smem_base + (s * STG_HALF) * 2;
        unsigned bbase = abase + A_HALF * 2;
        #pragma unroll
        for (int it = 0; it < 4; it++) {
            int idx = tid + it * 256;
            int row = idx >> 3, cc = (idx & 7) * 8;
            cp16(abase + (row * AST + cc) * 2,
                 &A[(size_t)(brow + row) * K + k0 + cc]);
        }
        #pragma unroll
        for (int it = 0; it < 4; it++) {
            int idx = tid + it * 256;
            int row = idx >> 4, cc = (idx & 15) * 8;
            cp16(bbase + (row * BST + cc) * 2,
                 &Bm[(size_t)(k0 + row) * N + bcol + cc]);
        }
    };

    issue(0, 0);     CP_COMMIT();
    issue(1, GBK);   CP_COMMIT();

    const int a_r = (lane & 15);
    const int a_c = (lane >> 4) * 8;
    for (int ti = 0; ti < T; ti++) {
        CP_WAIT(1);
        __syncthreads();

        int cs = ti % 3;
        unsigned abase = smem_base + (cs * STG_HALF) * 2;
        unsigned bbase = abase + A_HALF * 2;

        #pragma unroll
        for (int ks = 0; ks < 4; ks++) {
            const int kb = ks * 16;
            unsigned af[2][4], bf[8][2];
            #pragma unroll
            for (int i = 0; i < 2; i++) {
                int m0 = wm * 32 + i * 16;
                ldm_x4(af[i][0], af[i][1], af[i][2], af[i][3],
                       abase + ((m0 + a_r) * AST + kb + a_c) * 2);
            }
            #pragma unroll
            for (int jp = 0; jp < 4; jp++) {
                int n0 = wn * 64 + jp * 16;
                unsigned r0, r1, r2, r3;
                ldm_x4_t(r0, r1, r2, r3,
                         bbase + ((kb + a_r) * BST + n0 + a_c) * 2);
                bf[jp * 2][0]     = r0; bf[jp * 2][1]     = r1;
                bf[jp * 2 + 1][0] = r2; bf[jp * 2 + 1][1] = r3;
            }
            #pragma unroll
            for (int i = 0; i < 2; i++)
                #pragma unroll
                for (int j = 0; j < 8; j++)
                    MMA_F16(acc[i][j][0], acc[i][j][1], acc[i][j][2], acc[i][j][3],
                            af[i][0], af[i][1], af[i][2], af[i][3],
                            bf[j][0], bf[j][1]);

            // interleave the refill after the first compute chunk: first
            // ldmatrix batch runs immediately; copies overlap chunks 1..3
            if (ks == 0) {
                if (ti + 2 < T) { issue((ti + 2) % 3, (ti + 2) * GBK); }
                CP_COMMIT();
            }
        }
    }

    float bb[16];
    #pragma unroll
    for (int j = 0; j < 8; j++) {
        bb[j * 2]     = bias[bcol + wn * 64 + j * 8 + t * 2];
        bb[j * 2 + 1] = bias[bcol + wn * 64 + j * 8 + t * 2 + 1];
    }
    #pragma unroll
    for (int i = 0; i < 2; i++)
        #pragma unroll
        for (int j = 0; j < 8; j++) {
            acc[i][j][0] += bb[j * 2]; acc[i][j][1] += bb[j * 2 + 1];
            acc[i][j][2] += bb[j * 2]; acc[i][j][3] += bb[j * 2 + 1];
        }

    if (FUSED == 0) {
        #pragma unroll
        for (int i = 0; i < 2; i++) {
            int row = brow + wm * 32 + i * 16 + g;
            #pragma unroll
            for (int j = 0; j < 8; j++) {
                int col = bcol + wn * 64 + j * 8 + t * 2;
                float2 v0 = { acc[i][j][0], acc[i][j][1] };
                float2 v1 = { acc[i][j][2], acc[i][j][3] };
                *(float2*)&C[(size_t)row * N + col]       = v0;
                *(float2*)&C[(size_t)(row + 8) * N + col] = v1;
            }
        }
        return;
    }

    const int region = blockIdx.x >> 3;
    const int h      = ((blockIdx.x & 7) << 1) | wn;

    if (region == 2) {
        #pragma unroll
        for (int i = 0; i < 2; i++) {
            int grow = brow + wm * 32 + i * 16 + g;
            int nn = grow & (N_ - 1), bb_ = grow >> 10;
            size_t dst0 = ((size_t)(bb_ * H_ + h) * N_ + nn) * HD_;
            size_t dst1 = dst0 + 8 * HD_;
            #pragma unroll
            for (int j = 0; j < 8; j++) {
                int d = j * 8 + t * 2;
                *(__half2*)&g_vh[dst0 + d] = __floats2half2_rn(acc[i][j][0], acc[i][j][1]);
                *(__half2*)&g_vh[dst1 + d] = __floats2half2_rn(acc[i][j][2], acc[i][j][3]);
            }
        }
    } else {
        const float* scv = (region == 0) ? q_scale : k_scale;
        __half* outp     = (region == 0) ? g_qh : g_kh;
        const float rsmul = (region == 0) ? 0.125f : 1.0f;
        float scr[16];
        #pragma unroll
        for (int j = 0; j < 8; j++) {
            scr[j * 2]     = scv[j * 8 + t * 2];
            scr[j * 2 + 1] = scv[j * 8 + t * 2 + 1];
        }
        #pragma unroll
        for (int i = 0; i < 2; i++) {
            float ss0 = 0.f, ss1 = 0.f;
            #pragma unroll
            for (int j = 0; j < 8; j++) {
                ss0 += acc[i][j][0] * acc[i][j][0] + acc[i][j][1] * acc[i][j][1];
                ss1 += acc[i][j][2] * acc[i][j][2] + acc[i][j][3] * acc[i][j][3];
            }
            ss0 += __shfl_xor_sync(0xffffffffu, ss0, 1);
            ss0 += __shfl_xor_sync(0xffffffffu, ss0, 2);
            ss1 += __shfl_xor_sync(0xffffffffu, ss1, 1);
            ss1 += __shfl_xor_sync(0xffffffffu, ss1, 2);
            float rs0 = rsqrtf(ss0 * (1.0f / HD_) + 1e-6f) * rsmul;
            float rs1 = rsqrtf(ss1 * (1.0f / HD_) + 1e-6f) * rsmul;

            int grow = brow + wm * 32 + i * 16 + g;
            int nn = grow & (N_ - 1), bb_ = grow >> 10;
            size_t dst0 = ((size_t)(bb_ * H_ + h) * N_ + nn) * HD_;
            size_t dst1 = dst0 + 8 * HD_;
            #pragma unroll
            for (int j = 0; j < 4; j++) {
                int d = j * 8 + t * 2;
                float c00 = g_cos[nn * 32 + d],           s00 = g_sin[nn * 32 + d];
                float c01 = g_cos[nn * 32 + d + 1],       s01 = g_sin[nn * 32 + d + 1];
                float c10 = g_cos[(nn + 8) * 32 + d],     s10 = g_sin[(nn + 8) * 32 + d];
                float c11 = g_cos[(nn + 8) * 32 + d + 1], s11 = g_sin[(nn + 8) * 32 + d + 1];
                float a0 = acc[i][j][0] * rs0 * scr[j * 2];
                float a1 = acc[i][j][1] * rs0 * scr[j * 2 + 1];
                float p0 = acc[i][j + 4][0] * rs0 * scr[(j + 4) * 2];
                float p1 = acc[i][j + 4][1] * rs0 * scr[(j + 4) * 2 + 1];
                *(__half2*)&outp[dst0 + d]      = __floats2half2_rn(a0 * c00 - p0 * s00, a1 * c01 - p1 * s01);
                *(__half2*)&outp[dst0 + d + 32] = __floats2half2_rn(a0 * s00 + p0 * c00, a1 * s01 + p1 * c01);
                float e0 = acc[i][j][2] * rs1 * scr[j * 2];
                float e1 = acc[i][j][3] * rs1 * scr[j * 2 + 1];
                float q0 = acc[i][j + 4][2] * rs1 * scr[(j + 4) * 2];
                float q1 = acc[i][j + 4][3] * rs1 * scr[(j + 4) * 2 + 1];
                *(__half2*)&outp[dst1 + d]      = __floats2half2_rn(e0 * c10 - q0 * s10, e1 * c11 - q1 * s11);
                *(__half2*)&outp[dst1 + d + 32] = __floats2half2_rn(e0 * s10 + q0 * c10, e1 * s11 + q1 * c11);
            }
        }
    }
}

// ====== fp16 flash attention (R10/R14 exact): 4 warps x 32 rows, ones-column ===
#define KVST 88
#define KV_TILE_HALF (64 * KVST)
#define ATTN_SMEM_BYTES (6 * KV_TILE_HALF * 2)   // 67584

__global__ __launch_bounds__(128)
void attn_f16_kernel()
{
    extern __shared__ __half asm_[];
    const unsigned smem_base = (unsigned)__cvta_generic_to_shared(asm_);

    const int tid  = threadIdx.x;
    const int warp = tid >> 5;
    const int lane = tid & 31;
    const int g    = lane >> 2;
    const int t    = lane & 3;
    const int bh   = blockIdx.y;
    const int qbase = blockIdx.x * 128 + warp * 32;
    const size_t base = (size_t)bh * N_ * HD_;
    const float LOG2E = 1.44269504f;

    for (int i = tid; i < 3 * 64; i += 128) {
        int buf = i >> 6, row = i & 63;
        __half* p = asm_ + (size_t)(3 + buf) * KV_TILE_HALF + row * KVST + 64;
        p[0] = __float2half(1.0f);
        #pragma unroll
        for (int j = 1; j < 8; j++) p[j] = __float2half(0.0f);
    }

    unsigned qf[2][4][4];
    #pragma unroll
    for (int mt = 0; mt < 2; mt++) {
        const __half* Q0 = g_qh + base + (size_t)(qbase + mt * 16 + g) * HD_;
        const __half* Q1 = Q0 + 8 * HD_;
        #pragma unroll
        for (int kk = 0; kk < 4; kk++) {
            qf[mt][kk][0] = *(const unsigned*)&Q0[kk * 16 + 2 * t];
            qf[mt][kk][1] = *(const unsigned*)&Q1[kk * 16 + 2 * t];
            qf[mt][kk][2] = *(const unsigned*)&Q0[kk * 16 + 8 + 2 * t];
            qf[mt][kk][3] = *(const unsigned*)&Q1[kk * 16 + 8 + 2 * t];
        }
    }

    float of[2][8][4];
    float ofl[2][4];
    #pragma unroll
    for (int mt = 0; mt < 2; mt++) {
        #pragma unroll
        for (int j = 0; j < 8; j++)
            #pragma unroll
            for (int c = 0; c < 4; c++) of[mt][j][c] = 0.f;
        #pragma unroll
        for (int c = 0; c < 4; c++) ofl[mt][c] = 0.f;
    }
    float mrow[2][2] = {{-1e30f, -1e30f}, {-1e30f, -1e30f}};

    auto issue_tile = [&](int buf, int tile) {
        unsigned kb = smem_base + buf * KV_TILE_HALF * 2;
        unsigned vb = smem_base + (3 + buf) * KV_TILE_HALF * 2;
        const __half* kg = g_kh + base + (size_t)tile * 64 * HD_;
        const __half* vg = g_vh + base + (size_t)tile * 64 * HD_;
        #pragma unroll
        for (int it = 0; it < 4; it++) {
            int idx = tid + it * 128;
            int row = idx >> 3, cc = (idx & 7) * 8;
            cp16(kb + (row * KVST + cc) * 2, kg + row * HD_ + cc);
            cp16(vb + (row * KVST + cc) * 2, vg + row * HD_ + cc);
        }
    };

    issue_tile(0, 0); CP_COMMIT();
    issue_tile(1, 1); CP_COMMIT();

    const int lr = lane & 15;
    const int lc = (lane >> 4) * 8;

    for (int tile = 0; tile < N_ / 64; tile++) {
        CP_WAIT(1);
        __syncthreads();

        int bufi = tile % 3;
        unsigned kbuf = smem_base + bufi * KV_TILE_HALF * 2;
        unsigned vbuf = smem_base + (3 + bufi) * KV_TILE_HALF * 2;

        float sacc[2][8][4];
        #pragma unroll
        for (int mt = 0; mt < 2; mt++)
            #pragma unroll
            for (int j = 0; j < 8; j++)
                #pragma unroll
                for (int c = 0; c < 4; c++) sacc[mt][j][c] = 0.f;

        #pragma unroll
        for (int kk = 0; kk < 4; kk++) {
            #pragma unroll
            for (int jp = 0; jp < 4; jp++) {
                unsigned r0, r1, r2, r3;
                int krow = jp * 16 + ((lane >> 3) & 1) * 8 + (lane & 7);
                ldm_x4(r0, r1, r2, r3,
                       kbuf + (krow * KVST + kk * 16 + lc) * 2);
                MMA_F16(sacc[0][jp*2][0], sacc[0][jp*2][1], sacc[0][jp*2][2], sacc[0][jp*2][3],
                        qf[0][kk][0], qf[0][kk][1], qf[0][kk][2], qf[0][kk][3], r0, r2);
                MMA_F16(sacc[0][jp*2+1][0], sacc[0][jp*2+1][1], sacc[0][jp*2+1][2], sacc[0][jp*2+1][3],
                        qf[0][kk][0], qf[0][kk][1], qf[0][kk][2], qf[0][kk][3], r1, r3);
                MMA_F16(sacc[1][jp*2][0], sacc[1][jp*2][1], sacc[1][jp*2][2], sacc[1][jp*2][3],
                        qf[1][kk][0], qf[1][kk][1], qf[1][kk][2], qf[1][kk][3], r0, r2);
                MMA_F16(sacc[1][jp*2+1][0], sacc[1][jp*2+1][1], sacc[1][jp*2+1][2], sacc[1][jp*2+1][3],
                        qf[1][kk][0], qf[1][kk][1], qf[1][kk][2], qf[1][kk][3], r1, r3);
            }
        }

        unsigned ph2[2][8][2];
        #pragma unroll
        for (int mt = 0; mt < 2; mt++) {
            float mx0 = -1e30f, mx1 = -1e30f;
            #pragma unroll
            for (int j = 0; j < 8; j++) {
                mx0 = fmaxf(mx0, fmaxf(sacc[mt][j][0], sacc[mt][j][1]));
                mx1 = fmaxf(mx1, fmaxf(sacc[mt][j][2], sacc[mt][j][3]));
            }
            mx0 = fmaxf(mx0, __shfl_xor_sync(0xffffffffu, mx0, 1));
            mx0 = fmaxf(mx0, __shfl_xor_sync(0xffffffffu, mx0, 2));
            mx1 = fmaxf(mx1, __shfl_xor_sync(0xffffffffu, mx1, 1));
            mx1 = fmaxf(mx1, __shfl_xor_sync(0xffffffffu, mx1, 2));

            float mn0 = fmaxf(mrow[mt][0], mx0);
            float mn1 = fmaxf(mrow[mt][1], mx1);
            float corr0 = __expf(mrow[mt][0] - mn0);
            float corr1 = __expf(mrow[mt][1] - mn1);
            mrow[mt][0] = mn0; mrow[mt][1] = mn1;

            float me0 = mn0 * LOG2E, me1 = mn1 * LOG2E;
            #pragma unroll
            for (int j = 0; j < 8; j++) {
                float d0 = fmaf(sacc[mt][j][0], LOG2E, -me0);
                float d1 = fmaf(sacc[mt][j][1], LOG2E, -me0);
                float d2 = fmaf(sacc[mt][j][2], LOG2E, -me1);
                float d3 = fmaf(sacc[mt][j][3], LOG2E, -me1);
                unsigned u0 = packh2(d0, d1);
                unsigned u1 = packh2(d2, d3);
                asm("ex2.approx.f16x2 %0, %0;" : "+r"(u0));
                asm("ex2.approx.f16x2 %0, %0;" : "+r"(u1));
                ph2[mt][j][0] = u0;
                ph2[mt][j][1] = u1;
            }

            #pragma unroll
            for (int j = 0; j < 8; j++) {
                of[mt][j][0] *= corr0; of[mt][j][1] *= corr0;
                of[mt][j][2] *= corr1; of[mt][j][3] *= corr1;
            }
            ofl[mt][0] *= corr0; ofl[mt][1] *= corr0;
            ofl[mt][2] *= corr1; ofl[mt][3] *= corr1;
        }

        #pragma unroll
        for (int kk = 0; kk < 4; kk++) {
            #pragma unroll
            for (int jp = 0; jp < 4; jp++) {
                unsigned r0, r1, r2, r3;
                ldm_x4_t(r0, r1, r2, r3,
                         vbuf + ((kk * 16 + lr) * KVST + jp * 16 + lc) * 2);
                #pragma unroll
                for (int mt = 0; mt < 2; mt++) {
                    MMA_F16(of[mt][jp*2][0], of[mt][jp*2][1], of[mt][jp*2][2], of[mt][jp*2][3],
                            ph2[mt][kk*2][0], ph2[mt][kk*2][1],
                            ph2[mt][kk*2+1][0], ph2[mt][kk*2+1][1], r0, r1);
                    MMA_F16(of[mt][jp*2+1][0], of[mt][jp*2+1][1], of[mt][jp*2+1][2], of[mt][jp*2+1][3],
                            ph2[mt][kk*2][0], ph2[mt][kk*2][1],
                            ph2[mt][kk*2+1][0], ph2[mt][kk*2+1][1], r2, r3);
                }
            }
            {
                unsigned r0, r1, r2, r3;
                ldm_x4_t(r0, r1, r2, r3,
                         vbuf + ((kk * 16 + lr) * KVST + 64 + lc) * 2);
                #pragma unroll
                for (int mt = 0; mt < 2; mt++)
                    MMA_F16(ofl[mt][0], ofl[mt][1], ofl[mt][2], ofl[mt][3],
                            ph2[mt][kk*2][0], ph2[mt][kk*2][1],
                            ph2[mt][kk*2+1][0], ph2[mt][kk*2+1][1], r0, r1);
            }
        }

        if (tile + 2 < N_ / 64) issue_tile((tile + 2) % 3, tile + 2);
        CP_COMMIT();
    }

    const int b = bh >> 4, h = bh & 15;
    const int srcl = lane & 28;
    #pragma unroll
    for (int mt = 0; mt < 2; mt++) {
        float l0 = __shfl_sync(0xffffffffu, ofl[mt][0], srcl);
        float l1 = __shfl_sync(0xffffffffu, ofl[mt][2], srcl);
        float inv0 = 1.0f / l0;
        float inv1 = 1.0f / l1;
        size_t row0 = ((size_t)b * N_ + qbase + mt * 16 + g) * D_ + h * HD_;
        size_t row1 = row0 + (size_t)8 * D_;
        #pragma unroll
        for (int j = 0; j < 8; j++) {
            int d = j * 8 + t * 2;
            *(__half2*)&g_oh[row0 + d] = __floats2half2_rn(of[mt][j][0] * inv0, of[mt][j][1] * inv0);
            *(__half2*)&g_oh[row1 + d] = __floats2half2_rn(of[mt][j][2] * inv1, of[mt][j][3] * inv1);
        }
    }
}

// ---------------- launch ---------------------------------------------------------
extern "C" void kernel_launch(void* const* d_in, const int* in_sizes, int n_in,
                              void* d_out, int out_size)
{
    const float* x       = (const float*)d_in[0];
    const float* Wqkv    = (const float*)d_in[1];
    const float* bqkv    = (const float*)d_in[2];
    const float* Wout    = (const float*)d_in[3];
    const float* bout    = (const float*)d_in[4];
    const float* q_scale = (const float*)d_in[5];
    const float* k_scale = (const float*)d_in[6];
    float* out = (float*)d_out;

    __half *xh_p, *wqkvh_p, *wouth_p, *oh_p;
    cudaGetSymbolAddress((void**)&xh_p,    g_xh);
    cudaGetSymbolAddress((void**)&wqkvh_p, g_wqkvh);
    cudaGetSymbolAddress((void**)&wouth_p, g_wouth);
    cudaGetSymbolAddress((void**)&oh_p,    g_oh);

    cudaFuncSetAttribute(gemm_f16_core<0>,
                         cudaFuncAttributeMaxDynamicSharedMemorySize, GEMM_SMEM_BYTES);
    cudaFuncSetAttribute(gemm_f16_core<1>,
                         cudaFuncAttributeMaxDynamicSharedMemorySize, GEMM_SMEM_BYTES);
    cudaFuncSetAttribute(attn_f16_kernel,
                         cudaFuncAttributeMaxDynamicSharedMemorySize, ATTN_SMEM_BYTES);

    int total_n = CONV_N + N_ * 32;
    f2h_all_kernel<<<(total_n + 255) / 256, 256>>>(x, Wqkv, Wout);

    dim3 g1(N3_ / GBN, M_ / GBM);
    gemm_f16_core<1><<<g1, 256, GEMM_SMEM_BYTES>>>(
        xh_p, wqkvh_p, bqkv, nullptr, q_scale, k_scale, M_, N3_, D_);

    attn_f16_kernel<<<dim3(N_ / 128, B_ * H_), 128, ATTN_SMEM_BYTES>>>();

    dim3 g2(D_ / GBN, M_ / GBM);
    gemm_f16_core<0><<<g2, 256, GEMM_SMEM_BYTES>>>(
        oh_p, wouth_p, bout, out, nullptr, nullptr, M_, D_, D_);
}

// round 17
// speedup vs baseline: 1.7723x; 1.0266x over previous
#include <cuda_runtime.h>
#include <cuda_fp16.h>
#include <math.h>

#define B_  8
#define N_  1024
#define D_  1024
#define H_  16
#define HD_ 64
#define M_  (B_ * N_)
#define N3_ (3 * D_)

// ---------------- scratch ----------------------------------------------------
__device__ __half g_xh [(size_t)M_ * D_];
__device__ __half g_wqkvh[(size_t)D_ * N3_];
__device__ __half g_wouth[(size_t)D_ * D_];
__device__ __half g_qh [(size_t)B_ * H_ * N_ * HD_];
__device__ __half g_kh [(size_t)B_ * H_ * N_ * HD_];
__device__ __half g_vh [(size_t)B_ * H_ * N_ * HD_];
__device__ __half g_oh [(size_t)M_ * D_];
__device__ float  g_cos[N_ * 32];
__device__ float  g_sin[N_ * 32];

// ---------------- helpers -----------------------------------------------------
#define MMA_F16(d0,d1,d2,d3,a0,a1,a2,a3,b0,b1)                            \
    asm volatile(                                                          \
        "mma.sync.aligned.m16n8k16.row.col.f32.f16.f16.f32 "               \
        "{%0,%1,%2,%3},{%4,%5,%6,%7},{%8,%9},{%0,%1,%2,%3};\n"             \
        : "+f"(d0), "+f"(d1), "+f"(d2), "+f"(d3)                           \
        : "r"(a0), "r"(a1), "r"(a2), "r"(a3), "r"(b0), "r"(b1))

__device__ __forceinline__ void ldm_x4(unsigned& r0, unsigned& r1,
                                       unsigned& r2, unsigned& r3, unsigned a) {
    asm volatile("ldmatrix.sync.aligned.m8n8.x4.shared.b16 {%0,%1,%2,%3}, [%4];\n"
                 : "=r"(r0), "=r"(r1), "=r"(r2), "=r"(r3) : "r"(a));
}
__device__ __forceinline__ void ldm_x4_t(unsigned& r0, unsigned& r1,
                                         unsigned& r2, unsigned& r3, unsigned a) {
    asm volatile("ldmatrix.sync.aligned.m8n8.x4.trans.shared.b16 {%0,%1,%2,%3}, [%4];\n"
                 : "=r"(r0), "=r"(r1), "=r"(r2), "=r"(r3) : "r"(a));
}
__device__ __forceinline__ void cp16(unsigned smem_addr, const void* gptr) {
    asm volatile("cp.async.cg.shared.global [%0], [%1], 16;\n"
                 :: "r"(smem_addr), "l"(gptr));
}
#define CP_COMMIT() asm volatile("cp.async.commit_group;\n")
#define CP_WAIT(n)  asm volatile("cp.async.wait_group %0;\n" :: "n"(n))

__device__ __forceinline__ unsigned packh2(float a, float b) {
    __half2 h = __floats2half2_rn(a, b);
    return *(unsigned*)&h;
}

// -------- fused fp32 -> fp16 conversion + RoPE tables (one launch) -------------
#define X4_  (M_ * D_ / 4)
#define W14_ (D_ * N3_ / 4)
#define W24_ (D_ * D_ / 4)
#define CONV_N (X4_ + W14_ + W24_)
__global__ void f2h_all_kernel(const float* __restrict__ x,
                               const float* __restrict__ w1,
                               const float* __restrict__ w2) {
    int i = blockIdx.x * blockDim.x + threadIdx.x;
    if (i < CONV_N) {
        const float* src;
        __half* dst;
        int off;
        if (i < X4_) {
            src = x;  dst = g_xh;    off = i;
        } else if (i < X4_ + W14_) {
            src = w1; dst = g_wqkvh; off = i - X4_;
        } else {
            src = w2; dst = g_wouth; off = i - X4_ - W14_;
        }
        float4 v = ((const float4*)src)[off];
        ((__half2*)dst)[off * 2]     = __floats2half2_rn(v.x, v.y);
        ((__half2*)dst)[off * 2 + 1] = __floats2half2_rn(v.z, v.w);
    } else {
        int r = i - CONV_N;
        if (r >= N_ * 32) return;
        int n = r >> 5, j = r & 31;
        int pos = (j < 16) ? (n >> 5) : (n & 31);
        int jj  = (j < 16) ? j : (j - 16);
        float invf = exp2f(-(float)jj * (13.287712379549449f / 16.0f));
        float ang  = (float)pos * invf;
        g_cos[r] = cosf(ang);
        g_sin[r] = sinf(ang);
    }
}

// ====================== fp16 tensor-core GEMM + epilogues ======================
// Block 128x128, 8 warps = 4(M)x2(N), warp tile 32x64, occ 2.
// GBK=64 (16 k-tiles), 3-stage cp.async, refill at tail (R14 placement).
#define GBM 128
#define GBN 128
#define GBK 64
#define AST 72
#define BST 136
#define A_HALF (GBM * AST)     // 9216
#define B_HALF (GBK * BST)     // 8704
#define STG_HALF (A_HALF + B_HALF)
#define NSTAGE 3
#define GEMM_SMEM_BYTES (NSTAGE * STG_HALF * 2)   // 107520

template<int FUSED>
__global__ __launch_bounds__(256, 2)
void gemm_f16_core(const __half* __restrict__ A, const __half* __restrict__ Bm,
                   const float* __restrict__ bias, float* __restrict__ C,
                   const float* __restrict__ q_scale,
                   const float* __restrict__ k_scale,
                   int M, int N, int K)
{
    extern __shared__ __half sm[];
    const unsigned smem_base = (unsigned)__cvta_generic_to_shared(sm);

    const int tid  = threadIdx.x;
    const int warp = tid >> 5;
    const int lane = tid & 31;
    const int wm   = warp & 3;
    const int wn   = warp >> 2;
    const int g    = lane >> 2;
    const int t    = lane & 3;
    const int brow = blockIdx.y * GBM;
    const int bcol = blockIdx.x * GBN;

    float acc[2][8][4];
    #pragma unroll
    for (int i = 0; i < 2; i++)
        #pragma unroll
        for (int j = 0; j < 8; j++)
            #pragma unroll
            for (int c = 0; c < 4; c++) acc[i][j][c] = 0.f;

    const int T = K / GBK;

    auto issue = [&](int s, int k0) {
        unsigned abase = smem_base + (s * STG_HALF) * 2;
        unsigned bbase = abase + A_HALF * 2;
        #pragma unroll
        for (int it = 0; it < 4; it++) {
            int idx = tid + it * 256;
            int row = idx >> 3, cc = (idx & 7) * 8;
            cp16(abase + (row * AST + cc) * 2,
                 &A[(size_t)(brow + row) * K + k0 + cc]);
        }
        #pragma unroll
        for (int it = 0; it < 4; it++) {
            int idx = tid + it * 256;
            int row = idx >> 4, cc = (idx & 15) * 8;
            cp16(bbase + (row * BST + cc) * 2,
                 &Bm[(size_t)(k0 + row) * N + bcol + cc]);
        }
    };

    issue(0, 0);     CP_COMMIT();
    issue(1, GBK);   CP_COMMIT();

    const int a_r = (lane & 15);
    const int a_c = (lane >> 4) * 8;
    for (int ti = 0; ti < T; ti++) {
        CP_WAIT(1);
        __syncthreads();

        int cs = ti % 3;
        unsigned abase = smem_base + (cs * STG_HALF) * 2;
        unsigned bbase = abase + A_HALF * 2;

        #pragma unroll
        for (int ks = 0; ks < 4; ks++) {
            const int kb = ks * 16;
            unsigned af[2][4], bf[8][2];
            #pragma unroll
            for (int i = 0; i < 2; i++) {
                int m0 = wm * 32 + i * 16;
                ldm_x4(af[i][0], af[i][1], af[i][2], af[i][3],
                       abase + ((m0 + a_r) * AST + kb + a_c) * 2);
            }
            #pragma unroll
            for (int jp = 0; jp < 4; jp++) {
                int n0 = wn * 64 + jp * 16;
                unsigned r0, r1, r2, r3;
                ldm_x4_t(r0, r1, r2, r3,
                         bbase + ((kb + a_r) * BST + n0 + a_c) * 2);
                bf[jp * 2][0]     = r0; bf[jp * 2][1]     = r1;
                bf[jp * 2 + 1][0] = r2; bf[jp * 2 + 1][1] = r3;
            }
            #pragma unroll
            for (int i = 0; i < 2; i++)
                #pragma unroll
                for (int j = 0; j < 8; j++)
                    MMA_F16(acc[i][j][0], acc[i][j][1], acc[i][j][2], acc[i][j][3],
                            af[i][0], af[i][1], af[i][2], af[i][3],
                            bf[j][0], bf[j][1]);
        }

        if (ti + 2 < T) issue((ti + 2) % 3, (ti + 2) * GBK);
        CP_COMMIT();
    }

    float bb[16];
    #pragma unroll
    for (int j = 0; j < 8; j++) {
        bb[j * 2]     = bias[bcol + wn * 64 + j * 8 + t * 2];
        bb[j * 2 + 1] = bias[bcol + wn * 64 + j * 8 + t * 2 + 1];
    }
    #pragma unroll
    for (int i = 0; i < 2; i++)
        #pragma unroll
        for (int j = 0; j < 8; j++) {
            acc[i][j][0] += bb[j * 2]; acc[i][j][1] += bb[j * 2 + 1];
            acc[i][j][2] += bb[j * 2]; acc[i][j][3] += bb[j * 2 + 1];
        }

    if (FUSED == 0) {
        #pragma unroll
        for (int i = 0; i < 2; i++) {
            int row = brow + wm * 32 + i * 16 + g;
            #pragma unroll
            for (int j = 0; j < 8; j++) {
                int col = bcol + wn * 64 + j * 8 + t * 2;
                float2 v0 = { acc[i][j][0], acc[i][j][1] };
                float2 v1 = { acc[i][j][2], acc[i][j][3] };
                *(float2*)&C[(size_t)row * N + col]       = v0;
                *(float2*)&C[(size_t)(row + 8) * N + col] = v1;
            }
        }
        return;
    }

    const int region = blockIdx.x >> 3;
    const int h      = ((blockIdx.x & 7) << 1) | wn;

    if (region == 2) {
        #pragma unroll
        for (int i = 0; i < 2; i++) {
            int grow = brow + wm * 32 + i * 16 + g;
            int nn = grow & (N_ - 1), bb_ = grow >> 10;
            size_t dst0 = ((size_t)(bb_ * H_ + h) * N_ + nn) * HD_;
            size_t dst1 = dst0 + 8 * HD_;
            #pragma unroll
            for (int j = 0; j < 8; j++) {
                int d = j * 8 + t * 2;
                *(__half2*)&g_vh[dst0 + d] = __floats2half2_rn(acc[i][j][0], acc[i][j][1]);
                *(__half2*)&g_vh[dst1 + d] = __floats2half2_rn(acc[i][j][2], acc[i][j][3]);
            }
        }
    } else {
        const float* scv = (region == 0) ? q_scale : k_scale;
        __half* outp     = (region == 0) ? g_qh : g_kh;
        const float rsmul = (region == 0) ? 0.125f : 1.0f;
        float scr[16];
        #pragma unroll
        for (int j = 0; j < 8; j++) {
            scr[j * 2]     = scv[j * 8 + t * 2];
            scr[j * 2 + 1] = scv[j * 8 + t * 2 + 1];
        }
        #pragma unroll
        for (int i = 0; i < 2; i++) {
            float ss0 = 0.f, ss1 = 0.f;
            #pragma unroll
            for (int j = 0; j < 8; j++) {
                ss0 += acc[i][j][0] * acc[i][j][0] + acc[i][j][1] * acc[i][j][1];
                ss1 += acc[i][j][2] * acc[i][j][2] + acc[i][j][3] * acc[i][j][3];
            }
            ss0 += __shfl_xor_sync(0xffffffffu, ss0, 1);
            ss0 += __shfl_xor_sync(0xffffffffu, ss0, 2);
            ss1 += __shfl_xor_sync(0xffffffffu, ss1, 1);
            ss1 += __shfl_xor_sync(0xffffffffu, ss1, 2);
            float rs0 = rsqrtf(ss0 * (1.0f / HD_) + 1e-6f) * rsmul;
            float rs1 = rsqrtf(ss1 * (1.0f / HD_) + 1e-6f) * rsmul;

            int grow = brow + wm * 32 + i * 16 + g;
            int nn = grow & (N_ - 1), bb_ = grow >> 10;
            size_t dst0 = ((size_t)(bb_ * H_ + h) * N_ + nn) * HD_;
            size_t dst1 = dst0 + 8 * HD_;
            #pragma unroll
            for (int j = 0; j < 4; j++) {
                int d = j * 8 + t * 2;
                float c00 = g_cos[nn * 32 + d],           s00 = g_sin[nn * 32 + d];
                float c01 = g_cos[nn * 32 + d + 1],       s01 = g_sin[nn * 32 + d + 1];
                float c10 = g_cos[(nn + 8) * 32 + d],     s10 = g_sin[(nn + 8) * 32 + d];
                float c11 = g_cos[(nn + 8) * 32 + d + 1], s11 = g_sin[(nn + 8) * 32 + d + 1];
                float a0 = acc[i][j][0] * rs0 * scr[j * 2];
                float a1 = acc[i][j][1] * rs0 * scr[j * 2 + 1];
                float p0 = acc[i][j + 4][0] * rs0 * scr[(j + 4) * 2];
                float p1 = acc[i][j + 4][1] * rs0 * scr[(j + 4) * 2 + 1];
                *(__half2*)&outp[dst0 + d]      = __floats2half2_rn(a0 * c00 - p0 * s00, a1 * c01 - p1 * s01);
                *(__half2*)&outp[dst0 + d + 32] = __floats2half2_rn(a0 * s00 + p0 * c00, a1 * s01 + p1 * c01);
                float e0 = acc[i][j][2] * rs1 * scr[j * 2];
                float e1 = acc[i][j][3] * rs1 * scr[j * 2 + 1];
                float q0 = acc[i][j + 4][2] * rs1 * scr[(j + 4) * 2];
                float q1 = acc[i][j + 4][3] * rs1 * scr[(j + 4) * 2 + 1];
                *(__half2*)&outp[dst1 + d]      = __floats2half2_rn(e0 * c10 - q0 * s10, e1 * c11 - q1 * s11);
                *(__half2*)&outp[dst1 + d + 32] = __floats2half2_rn(e0 * s10 + q0 * c10, e1 * s11 + q1 * c11);
            }
        }
    }
}

// ====== fp16 flash attention (R10/R14 exact): 4 warps x 32 rows, ones-column ===
#define KVST 88
#define KV_TILE_HALF (64 * KVST)
#define ATTN_SMEM_BYTES (6 * KV_TILE_HALF * 2)   // 67584

__global__ __launch_bounds__(128)
void attn_f16_kernel()
{
    extern __shared__ __half asm_[];
    const unsigned smem_base = (unsigned)__cvta_generic_to_shared(asm_);

    const int tid  = threadIdx.x;
    const int warp = tid >> 5;
    const int lane = tid & 31;
    const int g    = lane >> 2;
    const int t    = lane & 3;
    const int bh   = blockIdx.y;
    const int qbase = blockIdx.x * 128 + warp * 32;
    const size_t base = (size_t)bh * N_ * HD_;
    const float LOG2E = 1.44269504f;

    for (int i = tid; i < 3 * 64; i += 128) {
        int buf = i >> 6, row = i & 63;
        __half* p = asm_ + (size_t)(3 + buf) * KV_TILE_HALF + row * KVST + 64;
        p[0] = __float2half(1.0f);
        #pragma unroll
        for (int j = 1; j < 8; j++) p[j] = __float2half(0.0f);
    }

    unsigned qf[2][4][4];
    #pragma unroll
    for (int mt = 0; mt < 2; mt++) {
        const __half* Q0 = g_qh + base + (size_t)(qbase + mt * 16 + g) * HD_;
        const __half* Q1 = Q0 + 8 * HD_;
        #pragma unroll
        for (int kk = 0; kk < 4; kk++) {
            qf[mt][kk][0] = *(const unsigned*)&Q0[kk * 16 + 2 * t];
            qf[mt][kk][1] = *(const unsigned*)&Q1[kk * 16 + 2 * t];
            qf[mt][kk][2] = *(const unsigned*)&Q0[kk * 16 + 8 + 2 * t];
            qf[mt][kk][3] = *(const unsigned*)&Q1[kk * 16 + 8 + 2 * t];
        }
    }

    float of[2][8][4];
    float ofl[2][4];
    #pragma unroll
    for (int mt = 0; mt < 2; mt++) {
        #pragma unroll
        for (int j = 0; j < 8; j++)
            #pragma unroll
            for (int c = 0; c < 4; c++) of[mt][j][c] = 0.f;
        #pragma unroll
        for (int c = 0; c < 4; c++) ofl[mt][c] = 0.f;
    }
    float mrow[2][2] = {{-1e30f, -1e30f}, {-1e30f, -1e30f}};

    auto issue_tile = [&](int buf, int tile) {
        unsigned kb = smem_base + buf * KV_TILE_HALF * 2;
        unsigned vb = smem_base + (3 + buf) * KV_TILE_HALF * 2;
        const __half* kg = g_kh + base + (size_t)tile * 64 * HD_;
        const __half* vg = g_vh + base + (size_t)tile * 64 * HD_;
        #pragma unroll
        for (int it = 0; it < 4; it++) {
            int idx = tid + it * 128;
            int row = idx >> 3, cc = (idx & 7) * 8;
            cp16(kb + (row * KVST + cc) * 2, kg + row * HD_ + cc);
            cp16(vb + (row * KVST + cc) * 2, vg + row * HD_ + cc);
        }
    };

    issue_tile(0, 0); CP_COMMIT();
    issue_tile(1, 1); CP_COMMIT();

    const int lr = lane & 15;
    const int lc = (lane >> 4) * 8;

    for (int tile = 0; tile < N_ / 64; tile++) {
        CP_WAIT(1);
        __syncthreads();

        int bufi = tile % 3;
        unsigned kbuf = smem_base + bufi * KV_TILE_HALF * 2;
        unsigned vbuf = smem_base + (3 + bufi) * KV_TILE_HALF * 2;

        float sacc[2][8][4];
        #pragma unroll
        for (int mt = 0; mt < 2; mt++)
            #pragma unroll
            for (int j = 0; j < 8; j++)
                #pragma unroll
                for (int c = 0; c < 4; c++) sacc[mt][j][c] = 0.f;

        #pragma unroll
        for (int kk = 0; kk < 4; kk++) {
            #pragma unroll
            for (int jp = 0; jp < 4; jp++) {
                unsigned r0, r1, r2, r3;
                int krow = jp * 16 + ((lane >> 3) & 1) * 8 + (lane & 7);
                ldm_x4(r0, r1, r2, r3,
                       kbuf + (krow * KVST + kk * 16 + lc) * 2);
                MMA_F16(sacc[0][jp*2][0], sacc[0][jp*2][1], sacc[0][jp*2][2], sacc[0][jp*2][3],
                        qf[0][kk][0], qf[0][kk][1], qf[0][kk][2], qf[0][kk][3], r0, r2);
                MMA_F16(sacc[0][jp*2+1][0], sacc[0][jp*2+1][1], sacc[0][jp*2+1][2], sacc[0][jp*2+1][3],
                        qf[0][kk][0], qf[0][kk][1], qf[0][kk][2], qf[0][kk][3], r1, r3);
                MMA_F16(sacc[1][jp*2][0], sacc[1][jp*2][1], sacc[1][jp*2][2], sacc[1][jp*2][3],
                        qf[1][kk][0], qf[1][kk][1], qf[1][kk][2], qf[1][kk][3], r0, r2);
                MMA_F16(sacc[1][jp*2+1][0], sacc[1][jp*2+1][1], sacc[1][jp*2+1][2], sacc[1][jp*2+1][3],
                        qf[1][kk][0], qf[1][kk][1], qf[1][kk][2], qf[1][kk][3], r1, r3);
            }
        }

        unsigned ph2[2][8][2];
        #pragma unroll
        for (int mt = 0; mt < 2; mt++) {
            float mx0 = -1e30f, mx1 = -1e30f;
            #pragma unroll
            for (int j = 0; j < 8; j++) {
                mx0 = fmaxf(mx0, fmaxf(sacc[mt][j][0], sacc[mt][j][1]));
                mx1 = fmaxf(mx1, fmaxf(sacc[mt][j][2], sacc[mt][j][3]));
            }
            mx0 = fmaxf(mx0, __shfl_xor_sync(0xffffffffu, mx0, 1));
            mx0 = fmaxf(mx0, __shfl_xor_sync(0xffffffffu, mx0, 2));
            mx1 = fmaxf(mx1, __shfl_xor_sync(0xffffffffu, mx1, 1));
            mx1 = fmaxf(mx1, __shfl_xor_sync(0xffffffffu, mx1, 2));

            float mn0 = fmaxf(mrow[mt][0], mx0);
            float mn1 = fmaxf(mrow[mt][1], mx1);
            float corr0 = __expf(mrow[mt][0] - mn0);
            float corr1 = __expf(mrow[mt][1] - mn1);
            mrow[mt][0] = mn0; mrow[mt][1] = mn1;

            float me0 = mn0 * LOG2E, me1 = mn1 * LOG2E;
            #pragma unroll
            for (int j = 0; j < 8; j++) {
                float d0 = fmaf(sacc[mt][j][0], LOG2E, -me0);
                float d1 = fmaf(sacc[mt][j][1], LOG2E, -me0);
                float d2 = fmaf(sacc[mt][j][2], LOG2E, -me1);
                float d3 = fmaf(sacc[mt][j][3], LOG2E, -me1);
                unsigned u0 = packh2(d0, d1);
                unsigned u1 = packh2(d2, d3);
                asm("ex2.approx.f16x2 %0, %0;" : "+r"(u0));
                asm("ex2.approx.f16x2 %0, %0;" : "+r"(u1));
                ph2[mt][j][0] = u0;
                ph2[mt][j][1] = u1;
            }

            #pragma unroll
            for (int j = 0; j < 8; j++) {
                of[mt][j][0] *= corr0; of[mt][j][1] *= corr0;
                of[mt][j][2] *= corr1; of[mt][j][3] *= corr1;
            }
            ofl[mt][0] *= corr0; ofl[mt][1] *= corr0;
            ofl[mt][2] *= corr1; ofl[mt][3] *= corr1;
        }

        #pragma unroll
        for (int kk = 0; kk < 4; kk++) {
            #pragma unroll
            for (int jp = 0; jp < 4; jp++) {
                unsigned r0, r1, r2, r3;
                ldm_x4_t(r0, r1, r2, r3,
                         vbuf + ((kk * 16 + lr) * KVST + jp * 16 + lc) * 2);
                #pragma unroll
                for (int mt = 0; mt < 2; mt++) {
                    MMA_F16(of[mt][jp*2][0], of[mt][jp*2][1], of[mt][jp*2][2], of[mt][jp*2][3],
                            ph2[mt][kk*2][0], ph2[mt][kk*2][1],
                            ph2[mt][kk*2+1][0], ph2[mt][kk*2+1][1], r0, r1);
                    MMA_F16(of[mt][jp*2+1][0], of[mt][jp*2+1][1], of[mt][jp*2+1][2], of[mt][jp*2+1][3],
                            ph2[mt][kk*2][0], ph2[mt][kk*2][1],
                            ph2[mt][kk*2+1][0], ph2[mt][kk*2+1][1], r2, r3);
                }
            }
            {
                unsigned r0, r1, r2, r3;
                ldm_x4_t(r0, r1, r2, r3,
                         vbuf + ((kk * 16 + lr) * KVST + 64 + lc) * 2);
                #pragma unroll
                for (int mt = 0; mt < 2; mt++)
                    MMA_F16(ofl[mt][0], ofl[mt][1], ofl[mt][2], ofl[mt][3],
                            ph2[mt][kk*2][0], ph2[mt][kk*2][1],
                            ph2[mt][kk*2+1][0], ph2[mt][kk*2+1][1], r0, r1);
            }
        }

        if (tile + 2 < N_ / 64) issue_tile((tile + 2) % 3, tile + 2);
        CP_COMMIT();
    }

    const int b = bh >> 4, h = bh & 15;
    const int srcl = lane & 28;
    #pragma unroll
    for (int mt = 0; mt < 2; mt++) {
        float l0 = __shfl_sync(0xffffffffu, ofl[mt][0], srcl);
        float l1 = __shfl_sync(0xffffffffu, ofl[mt][2], srcl);
        float inv0 = 1.0f / l0;
        float inv1 = 1.0f / l1;
        size_t row0 = ((size_t)b * N_ + qbase + mt * 16 + g) * D_ + h * HD_;
        size_t row1 = row0 + (size_t)8 * D_;
        #pragma unroll
        for (int j = 0; j < 8; j++) {
            int d = j * 8 + t * 2;
            *(__half2*)&g_oh[row0 + d] = __floats2half2_rn(of[mt][j][0] * inv0, of[mt][j][1] * inv0);
            *(__half2*)&g_oh[row1 + d] = __floats2half2_rn(of[mt][j][2] * inv1, of[mt][j][3] * inv1);
        }
    }
}

// ---------------- launch ---------------------------------------------------------
extern "C" void kernel_launch(void* const* d_in, const int* in_sizes, int n_in,
                              void* d_out, int out_size)
{
    const float* x       = (const float*)d_in[0];
    const float* Wqkv    = (const float*)d_in[1];
    const float* bqkv    = (const float*)d_in[2];
    const float* Wout    = (const float*)d_in[3];
    const float* bout    = (const float*)d_in[4];
    const float* q_scale = (const float*)d_in[5];
    const float* k_scale = (const float*)d_in[6];
    float* out = (float*)d_out;

    __half *xh_p, *wqkvh_p, *wouth_p, *oh_p;
    cudaGetSymbolAddress((void**)&xh_p,    g_xh);
    cudaGetSymbolAddress((void**)&wqkvh_p, g_wqkvh);
    cudaGetSymbolAddress((void**)&wouth_p, g_wouth);
    cudaGetSymbolAddress((void**)&oh_p,    g_oh);

    cudaFuncSetAttribute(gemm_f16_core<0>,
                         cudaFuncAttributeMaxDynamicSharedMemorySize, GEMM_SMEM_BYTES);
    cudaFuncSetAttribute(gemm_f16_core<1>,
                         cudaFuncAttributeMaxDynamicSharedMemorySize, GEMM_SMEM_BYTES);
    cudaFuncSetAttribute(attn_f16_kernel,
                         cudaFuncAttributeMaxDynamicSharedMemorySize, ATTN_SMEM_BYTES);

    int total_n = CONV_N + N_ * 32;
    f2h_all_kernel<<<(total_n + 255) / 256, 256>>>(x, Wqkv, Wout);

    dim3 g1(N3_ / GBN, M_ / GBM);
    gemm_f16_core<1><<<g1, 256, GEMM_SMEM_BYTES>>>(
        xh_p, wqkvh_p, bqkv, nullptr, q_scale, k_scale, M_, N3_, D_);

    attn_f16_kernel<<<dim3(N_ / 128, B_ * H_), 128, ATTN_SMEM_BYTES>>>();

    dim3 g2(D_ / GBN, M_ / GBM);
    gemm_f16_core<0><<<g2, 256, GEMM_SMEM_BYTES>>>(
        oh_p, wouth_p, bout, out, nullptr, nullptr, M_, D_, D_);
}